// round 1
// baseline (speedup 1.0000x reference)
#include <cuda_runtime.h>
#include <cstdint>

// GRU, H=1: scalar recurrence per batch row. B=16384 rows, T=4096 steps.
// One thread per row; latency-bound on the per-step chain:
//   h -> FFMA -> tanh(MUFU) -> FFMA -> tanh(MUFU) -> FFMA -> h'  (~44 cyc)
// sigmoid(a) = 0.5*tanh(0.5a)+0.5, with all 0.5 factors folded into
// per-thread constants so the chain stays 3 FFMA + 2 MUFU deep.

__device__ __forceinline__ float tanh_fast(float v) {
    float y;
    asm("tanh.approx.f32 %0, %1;" : "=f"(y) : "f"(v));
    return y;
}

// One GRU step. xv: input sample. h, hh(=0.5*h) carried state.
//   ra = 0.5*(x*wr + br_sum + h*ur)          -> tr = tanh(ra), r = 0.5+0.5*tr
//   za = 0.5*(x*wz + bz_sum + h*uz)          -> tz = tanh(za), z = 0.5+0.5*tz
//   gn = 0.5*(h*un + bhh_n)                  (= 0.5*gh_n)
//   narg = gx_n + r*gh_n = (gx_n + gn) + tr*gn
//   n = tanh(narg)
//   h' = (1-z)*n + z*h = n*(0.5-0.5tz) + (tz*hh + hh)
#define GRU_STEP(xv)                                   \
    {                                                  \
        float ax   = fmaf((xv), hwr, hbr);             \
        float az   = fmaf((xv), hwz, hbz);             \
        float an   = fmaf((xv), wn, bnx);              \
        float ra   = fmaf(h, hur, ax);                 \
        float za   = fmaf(h, huz, az);                 \
        float gn   = fmaf(h, hun, hbn);                \
        float tr   = tanh_fast(ra);                    \
        float tz   = tanh_fast(za);                    \
        float narg = fmaf(tr, gn, an + gn);            \
        float n    = tanh_fast(narg);                  \
        float omz  = fmaf(tz, -0.5f, 0.5f);            \
        float zh   = fmaf(tz, hh, hh);                 \
        h  = fmaf(n, omz, zh);                         \
        hh = 0.5f * h;                                 \
    }

__global__ void __launch_bounds__(64, 16)
gru_h1_kernel(const float* __restrict__ x,
              const float* __restrict__ w_ih,
              const float* __restrict__ w_hh,
              const float* __restrict__ b_ih,
              const float* __restrict__ b_hh,
              const float* __restrict__ fc_w,
              const float* __restrict__ fc_b,
              float* __restrict__ out,
              int B, int T)
{
    int b = blockIdx.x * blockDim.x + threadIdx.x;
    if (b >= B) return;

    // Scalar weights (uniform across threads; L1-broadcast after first hit).
    const float wr = w_ih[0], wz = w_ih[1], wn = w_ih[2];
    const float ur = w_hh[0], uz = w_hh[1], un = w_hh[2];
    const float hwr = 0.5f * wr;
    const float hwz = 0.5f * wz;
    const float hur = 0.5f * ur;
    const float huz = 0.5f * uz;
    const float hun = 0.5f * un;
    const float hbr = 0.5f * (b_ih[0] + b_hh[0]);
    const float hbz = 0.5f * (b_ih[1] + b_hh[1]);
    const float bnx = b_ih[2];            // gx_n bias
    const float hbn = 0.5f * b_hh[2];     // half of gh_n bias
    const float fw = fc_w[0], fb = fc_b[0];

    const float4* row = reinterpret_cast<const float4*>(x + (size_t)b * (size_t)T);

    float h = 0.0f, hh = 0.0f;

    // Chunked: 16 floats (4x float4) per chunk; prefetch next chunk while
    // computing current one (~700 cyc of compute covers DRAM latency).
    const int nch = T >> 4;  // T/16

    float4 cur0 = __ldcs(row + 0);
    float4 cur1 = __ldcs(row + 1);
    float4 cur2 = __ldcs(row + 2);
    float4 cur3 = __ldcs(row + 3);

    for (int c = 0; c < nch; ++c) {
        const int cn = (c + 1 < nch) ? (c + 1) : c;   // branchless: last chunk re-reads itself (L2 hit)
        const float4* nrow = row + (size_t)cn * 4;
        float4 nb0 = __ldcs(nrow + 0);
        float4 nb1 = __ldcs(nrow + 1);
        float4 nb2 = __ldcs(nrow + 2);
        float4 nb3 = __ldcs(nrow + 3);

        GRU_STEP(cur0.x); GRU_STEP(cur0.y); GRU_STEP(cur0.z); GRU_STEP(cur0.w);
        GRU_STEP(cur1.x); GRU_STEP(cur1.y); GRU_STEP(cur1.z); GRU_STEP(cur1.w);
        GRU_STEP(cur2.x); GRU_STEP(cur2.y); GRU_STEP(cur2.z); GRU_STEP(cur2.w);
        GRU_STEP(cur3.x); GRU_STEP(cur3.y); GRU_STEP(cur3.z); GRU_STEP(cur3.w);

        cur0 = nb0; cur1 = nb1; cur2 = nb2; cur3 = nb3;
    }

    out[b] = fmaf(h, fw, fb);
}

extern "C" void kernel_launch(void* const* d_in, const int* in_sizes, int n_in,
                              void* d_out, int out_size)
{
    const float* x    = (const float*)d_in[0];
    const float* w_ih = (const float*)d_in[1];
    const float* w_hh = (const float*)d_in[2];
    const float* b_ih = (const float*)d_in[3];
    const float* b_hh = (const float*)d_in[4];
    const float* fc_w = (const float*)d_in[5];
    const float* fc_b = (const float*)d_in[6];
    float* out = (float*)d_out;

    const int B = out_size;                 // 16384
    const int T = in_sizes[0] / B;          // 4096

    const int block = 64;
    const int grid = (B + block - 1) / block;
    gru_h1_kernel<<<grid, block>>>(x, w_ih, w_hh, b_ih, b_hh, fc_w, fc_b, out, B, T);
}